// round 16
// baseline (speedup 1.0000x reference)
#include <cuda_runtime.h>
#include <cstdint>

#define BATCH 4
#define DD 160
#define HH 192
#define WW 160
#define HW (HH * WW)                 // 30720
#define VOX (DD * HH * WW)           // 4,915,200

#define TD 8
#define TH 8
#define TW 32                        // TH*TW = 256 = TPB
#define TPB 256
#define VPT TD

// Static smem window: 13 x 13 x 44 = 29.7KB (+1KB reserve => 7 blocks/SM)
#define WDS 13
#define WHS 13
#define WPS 44
#define SZ  (WHS * WPS)              // 572, d-layer stride (2288B, 16B-aligned)
#define SMS (WDS * SZ)               // 7436 floats = 29.7KB

#define EPS 2e-4f                    // >> max fp slip (incl. incremental coord drift)

__global__ __launch_bounds__(TPB, 7) void st_affine_trilinear_v16(
    const float* __restrict__ vol,   // [B, D, H, W]
    const float* __restrict__ trf,   // [B, 4, 4]
    float* __restrict__ out)         // [B, D, H, W]
{
    __shared__ float sm[SMS];

    const int bi = blockIdx.x;
    const int wb = bi % 5;
    const int t1 = bi / 5;
    const int hb = t1 % 24;
    const int t2 = t1 / 24;
    const int db = t2 % 20;
    const int b  = t2 / 20;

    const int bd = db * TD, bh = hb * TH, bw = wb * TW;

    const float* A = trf + b * 16;
    const float a00 = A[0], a01 = A[1], a02 = A[2],  a03 = A[3];
    const float a10 = A[4], a11 = A[5], a12 = A[6],  a13 = A[7];
    const float a20 = A[8], a21 = A[9], a22 = A[10], a23 = A[11];

    const float cD = (DD - 1) * 0.5f, cH = (HH - 1) * 0.5f, cW = (WW - 1) * 0.5f;
    const float mD = (float)(DD - 1), mH = (float)(HH - 1), mW = (float)(WW - 1);
    const float* v = vol + b * VOX;

    // ---- window bounds: exact per-voxel fma chain evaluated at 8 tile corners ----
    float lodv =  1e30f, hidv = -1e30f;
    float lohv =  1e30f, hihv = -1e30f;
    float lowv =  1e30f, hiwv = -1e30f;
    #pragma unroll
    for (int c = 0; c < 8; c++) {
        const float pd = (float)(bd + ((c & 4) ? TD - 1 : 0)) - cD;
        const float ph = (float)(bh + ((c & 2) ? TH - 1 : 0)) - cH;
        const float pw = (float)(bw + ((c & 1) ? TW - 1 : 0)) - cW;
        const float ld = fmaf(a00, pd, fmaf(a01, ph, fmaf(a02, pw, a03))) + cD;
        const float lh = fmaf(a10, pd, fmaf(a11, ph, fmaf(a12, pw, a13))) + cH;
        const float lw = fmaf(a20, pd, fmaf(a21, ph, fmaf(a22, pw, a23))) + cW;
        lodv = fminf(lodv, ld); hidv = fmaxf(hidv, ld);
        lohv = fminf(lohv, lh); hihv = fmaxf(hihv, lh);
        lowv = fminf(lowv, lw); hiwv = fmaxf(hiwv, lw);
    }

    // epsilon-padded window: floor(t) provably within [il*, ih*-1]
    const int ild = max(0, (int)floorf(fminf(fmaxf(lodv, 0.f), mD) - EPS));
    const int ihd = min((int)floorf(fminf(fmaxf(hidv, 0.f), mD) + EPS), DD - 2) + 1;
    const int ilh = max(0, (int)floorf(fminf(fmaxf(lohv, 0.f), mH) - EPS));
    const int ihh = min((int)floorf(fminf(fmaxf(hihv, 0.f), mH) + EPS), HH - 2) + 1;
    const int ilw = max(0, (int)floorf(fminf(fmaxf(lowv, 0.f), mW) - EPS));
    const int ihw = min((int)floorf(fminf(fmaxf(hiwv, 0.f), mW) + EPS), WW - 2) + 1;

    const int ilw_al = ilw & ~3;       // 16B-aligned window start in w
    const int wdn = ihd - ild + 1;
    const int whn = ihh - ilh + 1;
    const int wal = ihw - ilw_al + 1;

    const int tid = threadIdx.x;
    const int wx  = tid & 31;
    const int hy  = (tid >> 5) & 7;

    const float ph  = (float)(bh + hy) - cH;
    const float pw  = (float)(bw + wx) - cW;
    const float pd0 = (float)bd - cD;

    const float t1d = fmaf(a01, ph, fmaf(a02, pw, a03)) + cD;
    const float t1h = fmaf(a11, ph, fmaf(a12, pw, a13)) + cH;
    const float t1w = fmaf(a21, ph, fmaf(a22, pw, a23)) + cW;

    if (wdn <= WDS && whn <= WHS && wal <= WPS) {
        // ---- cp.async fill: dynamic row width, global -> smem direct ----
        {
            const int nx4 = (wal + 3) >> 2;                        // float4 per row
            const int nj  = wdn * whn * nx4;
            const unsigned mwhn = (0x100000u + (unsigned)whn - 1u) / (unsigned)whn;
            const unsigned mnx  = (0x100000u + (unsigned)nx4 - 1u) / (unsigned)nx4;
            const int xmax4 = ((WW - ilw_al) >> 2) - 1;
            const float4* __restrict__ vsrc4 = reinterpret_cast<const float4*>(v);

            uint32_t sbase;
            asm("{ .reg .u64 t; cvta.to.shared.u64 t, %1; cvt.u32.u64 %0, t; }"
                : "=r"(sbase) : "l"((const void*)sm));

            for (int j = tid; j < nj; j += TPB) {
                const int row = (int)(((unsigned)j * mnx) >> 20);
                const int x4  = j - row * nx4;
                const int z   = (int)(((unsigned)row * mwhn) >> 20);
                const int y   = row - z * whn;
                const int x4c = min(x4, xmax4);
                const float4* src = vsrc4 +
                    (((ild + z) * HW + (ilh + y) * WW + ilw_al) >> 2) + x4c;
                const uint32_t dst = sbase + 4u * (uint32_t)(z * SZ + y * WPS + 4 * x4);
                asm volatile("cp.async.cg.shared.global [%0], [%1], 16;"
                             :: "r"(dst), "l"((const void*)src));
            }
            asm volatile("cp.async.commit_group;");
            asm volatile("cp.async.wait_group 0;");
        }
        __syncthreads();

        const int base = ild * SZ + ilh * WPS + ilw_al;
        int oidx = b * VOX + bd * HW + (bh + hy) * WW + bw + wx;

        const bool interior = (lodv >= 0.5f) && (hidv <= mD - 0.5f) &&
                              (lohv >= 0.5f) && (hihv <= mH - 0.5f) &&
                              (lowv >= 0.5f) && (hiwv <= mW - 0.5f);

        #define GATHER_BODY(f0d, f0h, f0w, td, th, tw)                           \
        {                                                                        \
            const float w1d = td - f0d;                                          \
            const float w1h = th - f0h;                                          \
            const float w1w = tw - f0w;                                          \
            const int a0 = (int)(fmaf(f0d, (float)SZ,                            \
                                 fmaf(f0h, (float)WPS, f0w))) - base;            \
            const int a1 = a0 + WPS;                                             \
            const int a2 = a0 + SZ;                                              \
            const int a3 = a2 + WPS;                                             \
            const float v000 = sm[a0],     v001 = sm[a0 + 1];                    \
            const float v010 = sm[a1],     v011 = sm[a1 + 1];                    \
            const float v100 = sm[a2],     v101 = sm[a2 + 1];                    \
            const float v110 = sm[a3],     v111 = sm[a3 + 1];                    \
            const float e00 = fmaf(w1w, v001 - v000, v000);                      \
            const float e01 = fmaf(w1w, v011 - v010, v010);                      \
            const float e10 = fmaf(w1w, v101 - v100, v100);                      \
            const float e11 = fmaf(w1w, v111 - v110, v110);                      \
            const float e0  = fmaf(w1h, e01 - e00, e00);                         \
            const float e1  = fmaf(w1h, e11 - e10, e10);                         \
            out[oidx] = fmaf(w1d, e1 - e0, e0);                                  \
            oidx += HW;                                                          \
        }

        if (interior) {
            // incremental coords (drift << EPS window margin)
            float ld = fmaf(a00, pd0, t1d);
            float lh = fmaf(a10, pd0, t1h);
            float lw = fmaf(a20, pd0, t1w);
            #pragma unroll
            for (int k = 0; k < VPT; k++) {
                const float f0d = floorf(ld);
                const float f0h = floorf(lh);
                const float f0w = floorf(lw);
                GATHER_BODY(f0d, f0h, f0w, ld, lh, lw)
                ld += a00; lh += a10; lw += a20;
            }
        } else {
            float ld = fmaf(a00, pd0, t1d);
            float lh = fmaf(a10, pd0, t1h);
            float lw = fmaf(a20, pd0, t1w);
            #pragma unroll
            for (int k = 0; k < VPT; k++) {
                const float td = fminf(fmaxf(ld, 0.0f), mD);
                const float th = fminf(fmaxf(lh, 0.0f), mH);
                const float tw = fminf(fmaxf(lw, 0.0f), mW);
                const float f0d = fminf(floorf(td), mD - 1.0f);
                const float f0h = fminf(floorf(th), mH - 1.0f);
                const float f0w = fminf(floorf(tw), mW - 1.0f);
                GATHER_BODY(f0d, f0h, f0w, td, th, tw)
                ld += a00; lh += a10; lw += a20;
            }
        }
        #undef GATHER_BODY
    } else {
        // ---- uniform fallback: direct global gather (reference semantics) ----
        int oidx = b * VOX + bd * HW + (bh + hy) * WW + bw + wx;
        #pragma unroll
        for (int k = 0; k < VPT; k++) {
            const float pd = pd0 + (float)k;
            const float ld = fmaf(a00, pd, t1d);
            const float lh = fmaf(a10, pd, t1h);
            const float lw = fmaf(a20, pd, t1w);

            const float td = fminf(fmaxf(ld, 0.0f), mD);
            const float th = fminf(fmaxf(lh, 0.0f), mH);
            const float tw = fminf(fmaxf(lw, 0.0f), mW);

            const float f0d = fminf(floorf(td), mD - 1.0f);
            const float f0h = fminf(floorf(th), mH - 1.0f);
            const float f0w = fminf(floorf(tw), mW - 1.0f);

            const float w1d = td - f0d;
            const float w1h = th - f0h;
            const float w1w = tw - f0w;

            const int c00 = (int)f0d * HW + (int)f0h * WW + (int)f0w;
            const int c01 = c00 + WW;
            const int c10 = c00 + HW;
            const int c11 = c10 + WW;

            const float v000 = __ldg(v + c00), v001 = __ldg(v + c00 + 1);
            const float v010 = __ldg(v + c01), v011 = __ldg(v + c01 + 1);
            const float v100 = __ldg(v + c10), v101 = __ldg(v + c10 + 1);
            const float v110 = __ldg(v + c11), v111 = __ldg(v + c11 + 1);

            const float e00 = fmaf(w1w, v001 - v000, v000);
            const float e01 = fmaf(w1w, v011 - v010, v010);
            const float e10 = fmaf(w1w, v101 - v100, v100);
            const float e11 = fmaf(w1w, v111 - v110, v110);
            const float e0  = fmaf(w1h, e01 - e00, e00);
            const float e1  = fmaf(w1h, e11 - e10, e10);

            out[oidx] = fmaf(w1d, e1 - e0, e0);
            oidx += HW;
        }
    }
}

extern "C" void kernel_launch(void* const* d_in, const int* in_sizes, int n_in,
                              void* d_out, int out_size) {
    const float* vol = (const float*)d_in[0];
    const float* trf = (const float*)d_in[1];
    float* out = (float*)d_out;
    const int blocks = BATCH * (DD / TD) * (HH / TH) * (WW / TW);   // 9600
    st_affine_trilinear_v16<<<blocks, TPB>>>(vol, trf, out);
}

// round 17
// speedup vs baseline: 1.1045x; 1.1045x over previous
#include <cuda_runtime.h>
#include <cstdint>

#define BATCH 4
#define DD 160
#define HH 192
#define WW 160
#define HW (HH * WW)                 // 30720
#define VOX (DD * HH * WW)           // 4,915,200

#define TD 8
#define TH 8
#define TW 32                        // TH*TW = 256 = TPB
#define TPB 256
#define VPT TD

// Static smem window: 13 x 13 x 48 (16B-aligned pitch) = 32.4KB (6 blocks/SM)
#define WDS 13
#define WHS 13
#define WPS 48
#define SZ  (WHS * WPS)              // 624, d-layer stride
#define SMS (WDS * SZ)               // 8112 floats = 32.4KB

#define EPS 2e-4f                    // >> max fp slip (incl. incremental coord drift)

__global__ __launch_bounds__(TPB) void st_affine_trilinear_v17(
    const float* __restrict__ vol,   // [B, D, H, W]
    const float* __restrict__ trf,   // [B, 4, 4]
    float* __restrict__ out)         // [B, D, H, W]
{
    __shared__ float sm[SMS];
    __shared__ int sbnd[8];          // ild, ihd, ilh, ihh, ilw, ihw, interior, (pad)

    const int bi = blockIdx.x;
    const int wb = bi % 5;
    const int t1 = bi / 5;
    const int hb = t1 % 24;
    const int t2 = t1 / 24;
    const int db = t2 % 20;
    const int b  = t2 / 20;

    const int bd = db * TD, bh = hb * TH, bw = wb * TW;

    const float* A = trf + b * 16;
    const float a00 = A[0], a01 = A[1], a02 = A[2],  a03 = A[3];
    const float a10 = A[4], a11 = A[5], a12 = A[6],  a13 = A[7];
    const float a20 = A[8], a21 = A[9], a22 = A[10], a23 = A[11];

    const float cD = (DD - 1) * 0.5f, cH = (HH - 1) * 0.5f, cW = (WW - 1) * 0.5f;
    const float mD = (float)(DD - 1), mH = (float)(HH - 1), mW = (float)(WW - 1);
    const float* v = vol + b * VOX;

    const int tid = threadIdx.x;

    // ---- warp 0 only: window bounds from the 8 tile corners; broadcast via smem ----
    if (tid < 32) {
        float lodv =  1e30f, hidv = -1e30f;
        float lohv =  1e30f, hihv = -1e30f;
        float lowv =  1e30f, hiwv = -1e30f;
        #pragma unroll
        for (int c = 0; c < 8; c++) {
            const float pd = (float)(bd + ((c & 4) ? TD - 1 : 0)) - cD;
            const float ph = (float)(bh + ((c & 2) ? TH - 1 : 0)) - cH;
            const float pw = (float)(bw + ((c & 1) ? TW - 1 : 0)) - cW;
            const float ld = fmaf(a00, pd, fmaf(a01, ph, fmaf(a02, pw, a03))) + cD;
            const float lh = fmaf(a10, pd, fmaf(a11, ph, fmaf(a12, pw, a13))) + cH;
            const float lw = fmaf(a20, pd, fmaf(a21, ph, fmaf(a22, pw, a23))) + cW;
            lodv = fminf(lodv, ld); hidv = fmaxf(hidv, ld);
            lohv = fminf(lohv, lh); hihv = fmaxf(hihv, lh);
            lowv = fminf(lowv, lw); hiwv = fmaxf(hiwv, lw);
        }

        // epsilon-padded window: floor(t) provably within [il*, ih*-1]
        const int ild = max(0, (int)floorf(fminf(fmaxf(lodv, 0.f), mD) - EPS));
        const int ihd = min((int)floorf(fminf(fmaxf(hidv, 0.f), mD) + EPS), DD - 2) + 1;
        const int ilh = max(0, (int)floorf(fminf(fmaxf(lohv, 0.f), mH) - EPS));
        const int ihh = min((int)floorf(fminf(fmaxf(hihv, 0.f), mH) + EPS), HH - 2) + 1;
        const int ilw = max(0, (int)floorf(fminf(fmaxf(lowv, 0.f), mW) - EPS));
        const int ihw = min((int)floorf(fminf(fmaxf(hiwv, 0.f), mW) + EPS), WW - 2) + 1;

        const int interior = (lodv >= 0.5f) && (hidv <= mD - 0.5f) &&
                             (lohv >= 0.5f) && (hihv <= mH - 0.5f) &&
                             (lowv >= 0.5f) && (hiwv <= mW - 0.5f);

        if (tid == 0) {
            sbnd[0] = ild; sbnd[1] = ihd;
            sbnd[2] = ilh; sbnd[3] = ihh;
            sbnd[4] = ilw; sbnd[5] = ihw;
            sbnd[6] = interior;
        }
    }

    // per-thread hoisted constants (overlaps warp-0 work)
    const int wx  = tid & 31;
    const int hy  = (tid >> 5) & 7;
    const float ph  = (float)(bh + hy) - cH;
    const float pw  = (float)(bw + wx) - cW;
    const float pd0 = (float)bd - cD;
    const float t1d = fmaf(a01, ph, fmaf(a02, pw, a03)) + cD;
    const float t1h = fmaf(a11, ph, fmaf(a12, pw, a13)) + cH;
    const float t1w = fmaf(a21, ph, fmaf(a22, pw, a23)) + cW;

    __syncthreads();

    const int ild = sbnd[0], ihd = sbnd[1];
    const int ilh = sbnd[2], ihh = sbnd[3];
    const int ilw = sbnd[4], ihw = sbnd[5];
    const bool interior = (sbnd[6] != 0);

    const int ilw_al = ilw & ~3;       // 16B-aligned window start in w
    const int wdn = ihd - ild + 1;
    const int whn = ihh - ilh + 1;
    const int wal = ihw - ilw_al + 1;

    if (wdn <= WDS && whn <= WHS && wal <= WPS) {
        // ---- cp.async fill: dynamic row width, global -> smem direct ----
        {
            const int nx4 = (wal + 3) >> 2;                        // float4 per row
            const int nj  = wdn * whn * nx4;
            const unsigned mwhn = (0x100000u + (unsigned)whn - 1u) / (unsigned)whn;
            const unsigned mnx  = (0x100000u + (unsigned)nx4 - 1u) / (unsigned)nx4;
            const int xmax4 = ((WW - ilw_al) >> 2) - 1;
            const float4* __restrict__ vsrc4 = reinterpret_cast<const float4*>(v);

            uint32_t sbase;
            asm("{ .reg .u64 t; cvta.to.shared.u64 t, %1; cvt.u32.u64 %0, t; }"
                : "=r"(sbase) : "l"((const void*)sm));

            for (int j = tid; j < nj; j += TPB) {
                const int row = (int)(((unsigned)j * mnx) >> 20);
                const int x4  = j - row * nx4;
                const int z   = (int)(((unsigned)row * mwhn) >> 20);
                const int y   = row - z * whn;
                const int x4c = min(x4, xmax4);
                const float4* src = vsrc4 +
                    (((ild + z) * HW + (ilh + y) * WW + ilw_al) >> 2) + x4c;
                const uint32_t dst = sbase + 4u * (uint32_t)(z * SZ + y * WPS + 4 * x4);
                asm volatile("cp.async.cg.shared.global [%0], [%1], 16;"
                             :: "r"(dst), "l"((const void*)src));
            }
            asm volatile("cp.async.commit_group;");
            asm volatile("cp.async.wait_group 0;");
        }
        __syncthreads();

        const int base = ild * SZ + ilh * WPS + ilw_al;
        int oidx = b * VOX + bd * HW + (bh + hy) * WW + bw + wx;

        #define GATHER_BODY(f0d, f0h, f0w, td, th, tw)                           \
        {                                                                        \
            const float w1d = td - f0d;                                          \
            const float w1h = th - f0h;                                          \
            const float w1w = tw - f0w;                                          \
            const int a0 = (int)(fmaf(f0d, (float)SZ,                            \
                                 fmaf(f0h, (float)WPS, f0w))) - base;            \
            const int a1 = a0 + WPS;                                             \
            const int a2 = a0 + SZ;                                              \
            const int a3 = a2 + WPS;                                             \
            const float v000 = sm[a0],     v001 = sm[a0 + 1];                    \
            const float v010 = sm[a1],     v011 = sm[a1 + 1];                    \
            const float v100 = sm[a2],     v101 = sm[a2 + 1];                    \
            const float v110 = sm[a3],     v111 = sm[a3 + 1];                    \
            const float e00 = fmaf(w1w, v001 - v000, v000);                      \
            const float e01 = fmaf(w1w, v011 - v010, v010);                      \
            const float e10 = fmaf(w1w, v101 - v100, v100);                      \
            const float e11 = fmaf(w1w, v111 - v110, v110);                      \
            const float e0  = fmaf(w1h, e01 - e00, e00);                         \
            const float e1  = fmaf(w1h, e11 - e10, e10);                         \
            out[oidx] = fmaf(w1d, e1 - e0, e0);                                  \
            oidx += HW;                                                          \
        }

        if (interior) {
            // incremental coords (drift << EPS window margin)
            float ld = fmaf(a00, pd0, t1d);
            float lh = fmaf(a10, pd0, t1h);
            float lw = fmaf(a20, pd0, t1w);
            #pragma unroll
            for (int k = 0; k < VPT; k++) {
                const float f0d = floorf(ld);
                const float f0h = floorf(lh);
                const float f0w = floorf(lw);
                GATHER_BODY(f0d, f0h, f0w, ld, lh, lw)
                ld += a00; lh += a10; lw += a20;
            }
        } else {
            float ld = fmaf(a00, pd0, t1d);
            float lh = fmaf(a10, pd0, t1h);
            float lw = fmaf(a20, pd0, t1w);
            #pragma unroll
            for (int k = 0; k < VPT; k++) {
                const float td = fminf(fmaxf(ld, 0.0f), mD);
                const float th = fminf(fmaxf(lh, 0.0f), mH);
                const float tw = fminf(fmaxf(lw, 0.0f), mW);
                const float f0d = fminf(floorf(td), mD - 1.0f);
                const float f0h = fminf(floorf(th), mH - 1.0f);
                const float f0w = fminf(floorf(tw), mW - 1.0f);
                GATHER_BODY(f0d, f0h, f0w, td, th, tw)
                ld += a00; lh += a10; lw += a20;
            }
        }
        #undef GATHER_BODY
    } else {
        // ---- uniform fallback: direct global gather (reference semantics) ----
        int oidx = b * VOX + bd * HW + (bh + hy) * WW + bw + wx;
        #pragma unroll
        for (int k = 0; k < VPT; k++) {
            const float pd = pd0 + (float)k;
            const float ld = fmaf(a00, pd, t1d);
            const float lh = fmaf(a10, pd, t1h);
            const float lw = fmaf(a20, pd, t1w);

            const float td = fminf(fmaxf(ld, 0.0f), mD);
            const float th = fminf(fmaxf(lh, 0.0f), mH);
            const float tw = fminf(fmaxf(lw, 0.0f), mW);

            const float f0d = fminf(floorf(td), mD - 1.0f);
            const float f0h = fminf(floorf(th), mH - 1.0f);
            const float f0w = fminf(floorf(tw), mW - 1.0f);

            const float w1d = td - f0d;
            const float w1h = th - f0h;
            const float w1w = tw - f0w;

            const int c00 = (int)f0d * HW + (int)f0h * WW + (int)f0w;
            const int c01 = c00 + WW;
            const int c10 = c00 + HW;
            const int c11 = c10 + WW;

            const float v000 = __ldg(v + c00), v001 = __ldg(v + c00 + 1);
            const float v010 = __ldg(v + c01), v011 = __ldg(v + c01 + 1);
            const float v100 = __ldg(v + c10), v101 = __ldg(v + c10 + 1);
            const float v110 = __ldg(v + c11), v111 = __ldg(v + c11 + 1);

            const float e00 = fmaf(w1w, v001 - v000, v000);
            const float e01 = fmaf(w1w, v011 - v010, v010);
            const float e10 = fmaf(w1w, v101 - v100, v100);
            const float e11 = fmaf(w1w, v111 - v110, v110);
            const float e0  = fmaf(w1h, e01 - e00, e00);
            const float e1  = fmaf(w1h, e11 - e10, e10);

            out[oidx] = fmaf(w1d, e1 - e0, e0);
            oidx += HW;
        }
    }
}

extern "C" void kernel_launch(void* const* d_in, const int* in_sizes, int n_in,
                              void* d_out, int out_size) {
    const float* vol = (const float*)d_in[0];
    const float* trf = (const float*)d_in[1];
    float* out = (float*)d_out;
    const int blocks = BATCH * (DD / TD) * (HH / TH) * (WW / TW);   // 9600
    st_affine_trilinear_v17<<<blocks, TPB>>>(vol, trf, out);
}